// round 1
// baseline (speedup 1.0000x reference)
#include <cuda_runtime.h>
#include <cuda_bf16.h>

#define NPART 2048
#define HID 32
#define CUTOFF2 6.25f

// Scratch accumulator (no device mallocs allowed)
__device__ double g_energy_accum;

__global__ void pp_zero_kernel() {
    g_energy_accum = 0.0;
}

__global__ void __launch_bounds__(128) pp_pair_kernel(
    const float* __restrict__ xyz,
    const float* __restrict__ cell_diag,
    const float* __restrict__ W1,
    const float* __restrict__ b1,
    const float* __restrict__ W2,
    const float* __restrict__ b2)
{
    __shared__ float sW1[HID];
    __shared__ float sb1[HID];
    __shared__ float sW2[HID];
    __shared__ float sRed[4];  // per-warp partial sums (128 threads = 4 warps)

    const int tid = threadIdx.x;
    if (tid < HID) {
        sW1[tid] = W1[tid];
        sb1[tid] = b1[tid];
        sW2[tid] = W2[tid];
    }
    __syncthreads();

    const float Lx = cell_diag[0];
    const float Ly = cell_diag[1];
    const float Lz = cell_diag[2];
    const float hLx = 0.5f * Lx, hLy = 0.5f * Ly, hLz = 0.5f * Lz;
    const float b2v = b2[0];

    float acc = 0.0f;

    // Each block handles two rows: i and NPART-1-i  => ~NPART pairs per block (balanced)
    const int rows[2] = { (int)blockIdx.x, NPART - 1 - (int)blockIdx.x };

    #pragma unroll
    for (int r = 0; r < 2; ++r) {
        const int i = rows[r];
        const float xi = xyz[3 * i + 0];
        const float yi = xyz[3 * i + 1];
        const float zi = xyz[3 * i + 2];

        for (int j = i + 1 + tid; j < NPART; j += 128) {
            float dx = xyz[3 * j + 0] - xi;
            float dy = xyz[3 * j + 1] - yi;
            float dz = xyz[3 * j + 2] - zi;

            // minimum-image convention, matching the reference exactly
            if (dx >= hLx) dx -= Lx; else if (dx < -hLx) dx += Lx;
            if (dy >= hLy) dy -= Ly; else if (dy < -hLy) dy += Ly;
            if (dz >= hLz) dz -= Lz; else if (dz < -hLz) dz += Lz;

            const float r2 = dx * dx + dy * dy + dz * dz;
            if (r2 < CUTOFF2 && r2 > 0.0f) {
                const float d = sqrtf(r2);
                float e = b2v;
                #pragma unroll
                for (int k = 0; k < HID; ++k) {
                    e = fmaf(sW2[k], tanhf(fmaf(d, sW1[k], sb1[k])), e);
                }
                acc += e;
            }
        }
    }

    // warp reduce
    #pragma unroll
    for (int off = 16; off > 0; off >>= 1)
        acc += __shfl_xor_sync(0xFFFFFFFFu, acc, off);

    const int warp = tid >> 5;
    const int lane = tid & 31;
    if (lane == 0) sRed[warp] = acc;
    __syncthreads();

    if (tid == 0) {
        float bsum = sRed[0] + sRed[1] + sRed[2] + sRed[3];
        atomicAdd(&g_energy_accum, (double)bsum);
    }
}

__global__ void pp_write_kernel(float* __restrict__ out) {
    out[0] = (float)g_energy_accum;
}

extern "C" void kernel_launch(void* const* d_in, const int* in_sizes, int n_in,
                              void* d_out, int out_size) {
    const float* xyz       = (const float*)d_in[0];
    const float* cell_diag = (const float*)d_in[1];
    const float* W1        = (const float*)d_in[2];
    const float* b1        = (const float*)d_in[3];
    const float* W2        = (const float*)d_in[4];
    const float* b2        = (const float*)d_in[5];
    float* out = (float*)d_out;

    pp_zero_kernel<<<1, 1>>>();
    pp_pair_kernel<<<NPART / 2, 128>>>(xyz, cell_diag, W1, b1, W2, b2);
    pp_write_kernel<<<1, 1>>>(out);
}

// round 2
// speedup vs baseline: 1.7436x; 1.7436x over previous
#include <cuda_runtime.h>
#include <cuda_bf16.h>

#define NPART 2048
#define HID 32
#define CUTOFF2 6.25f
#define NTHREADS 128
#define NWARPS 4
#define BUFSZ 64   // per-warp distance ring buffer (power of 2, >= 2*32)

__device__ double g_energy_accum = 0.0;
__device__ unsigned int g_block_count = 0;

__device__ __forceinline__ float mlp_energy(float d,
                                            const float* __restrict__ sW1,
                                            const float* __restrict__ sb1,
                                            const float* __restrict__ sW2,
                                            float b2v)
{
    float e = b2v;
    #pragma unroll
    for (int k = 0; k < HID; ++k) {
        e = fmaf(sW2[k], tanhf(fmaf(d, sW1[k], sb1[k])), e);
    }
    return e;
}

__global__ void __launch_bounds__(NTHREADS) pp_fused_kernel(
    const float* __restrict__ xyz,
    const float* __restrict__ cell_diag,
    const float* __restrict__ W1,
    const float* __restrict__ b1,
    const float* __restrict__ W2,
    const float* __restrict__ b2,
    float* __restrict__ out)
{
    __shared__ float sx[NPART], sy[NPART], sz[NPART];
    __shared__ float sW1[HID], sb1[HID], sW2[HID];
    __shared__ float sBuf[NWARPS * BUFSZ];
    __shared__ float sRed[NWARPS];

    const int tid  = threadIdx.x;
    const int warp = tid >> 5;
    const int lane = tid & 31;

    if (tid < HID) {
        sW1[tid] = W1[tid];
        sb1[tid] = b1[tid];
        sW2[tid] = W2[tid];
    }
    // SoA preload of all coordinates (coalesced global reads)
    for (int idx = tid; idx < NPART * 3; idx += NTHREADS) {
        const float v = xyz[idx];
        const int p = idx / 3, c = idx - 3 * p;
        if (c == 0)      sx[p] = v;
        else if (c == 1) sy[p] = v;
        else             sz[p] = v;
    }
    __syncthreads();

    const float Lx = cell_diag[0], Ly = cell_diag[1], Lz = cell_diag[2];
    const float hLx = 0.5f * Lx, hLy = 0.5f * Ly, hLz = 0.5f * Lz;
    const float b2v = b2[0];

    float acc = 0.0f;
    unsigned int cnt = 0, processed = 0;   // per-warp (uniform) ring state
    float* buf = &sBuf[warp * BUFSZ];

    const int rows[2] = { (int)blockIdx.x, NPART - 1 - (int)blockIdx.x };

    #pragma unroll
    for (int r = 0; r < 2; ++r) {
        const int i = rows[r];
        const float xi = sx[i], yi = sy[i], zi = sz[i];

        // warp-uniform base loop; lane handles j = base + lane
        for (int base = i + 1 + warp * 32; base < NPART; base += NTHREADS) {
            const int j = base + lane;
            const bool valid = (j < NPART);

            float dx = 0.f, dy = 0.f, dz = 0.f;
            if (valid) {
                dx = sx[j] - xi;
                dy = sy[j] - yi;
                dz = sz[j] - zi;
                if (dx >= hLx) dx -= Lx; else if (dx < -hLx) dx += Lx;
                if (dy >= hLy) dy -= Ly; else if (dy < -hLy) dy += Ly;
                if (dz >= hLz) dz -= Lz; else if (dz < -hLz) dz += Lz;
            }
            const float r2 = dx * dx + dy * dy + dz * dz;
            const bool hit = valid && (r2 < CUTOFF2) && (r2 > 0.0f);

            const unsigned int bal = __ballot_sync(0xFFFFFFFFu, hit);
            if (hit) {
                const unsigned int pos =
                    (cnt + __popc(bal & ((1u << lane) - 1u))) & (BUFSZ - 1);
                buf[pos] = sqrtf(r2);
            }
            cnt += __popc(bal);
            __syncwarp();

            if (cnt - processed >= 32) {
                const float d = buf[(processed + lane) & (BUFSZ - 1)];
                acc += mlp_energy(d, sW1, sb1, sW2, b2v);
                processed += 32;
                __syncwarp();
            }
        }
    }

    // flush remainder (< 32 pending distances)
    {
        const unsigned int rem = cnt - processed;
        if (rem > 0) {
            const float d = (lane < rem)
                ? buf[(processed + lane) & (BUFSZ - 1)] : 1.0f;
            const float e = mlp_energy(d, sW1, sb1, sW2, b2v);
            if (lane < rem) acc += e;
        }
    }

    // block reduction
    #pragma unroll
    for (int off = 16; off > 0; off >>= 1)
        acc += __shfl_xor_sync(0xFFFFFFFFu, acc, off);
    if (lane == 0) sRed[warp] = acc;
    __syncthreads();

    if (tid == 0) {
        const float bsum = sRed[0] + sRed[1] + sRed[2] + sRed[3];
        atomicAdd(&g_energy_accum, (double)bsum);
        __threadfence();
        const unsigned int ticket = atomicAdd(&g_block_count, 1u);
        if (ticket == gridDim.x - 1) {
            // all partials visible; finalize and reset for next graph replay
            const double total = atomicAdd(&g_energy_accum, 0.0);
            out[0] = (float)total;
            g_energy_accum = 0.0;
            g_block_count = 0;
            __threadfence();
        }
    }
}

extern "C" void kernel_launch(void* const* d_in, const int* in_sizes, int n_in,
                              void* d_out, int out_size) {
    const float* xyz       = (const float*)d_in[0];
    const float* cell_diag = (const float*)d_in[1];
    const float* W1        = (const float*)d_in[2];
    const float* b1        = (const float*)d_in[3];
    const float* W2        = (const float*)d_in[4];
    const float* b2        = (const float*)d_in[5];
    float* out = (float*)d_out;

    pp_fused_kernel<<<NPART / 2, NTHREADS>>>(xyz, cell_diag, W1, b1, W2, b2, out);
}

// round 5
// speedup vs baseline: 2.2821x; 1.3088x over previous
#include <cuda_runtime.h>
#include <cuda_bf16.h>

#define NPART 2048
#define HID 32
#define CUTOFF2 6.25f
#define NTHREADS 128
#define NWARPS 4
#define BUFSZ 64   // per-warp distance ring buffer (power of 2, >= 2*32)

__device__ double g_energy_accum = 0.0;
__device__ unsigned int g_block_count = 0;

__device__ __forceinline__ float mlp_energy(float d,
                                            const float* __restrict__ sW1,
                                            const float* __restrict__ sb1,
                                            const float* __restrict__ sW2,
                                            float b2v)
{
    float e = b2v;
    #pragma unroll
    for (int k = 0; k < HID; ++k) {
        e = fmaf(sW2[k], tanhf(fmaf(d, sW1[k], sb1[k])), e);
    }
    return e;
}

__global__ void __launch_bounds__(NTHREADS) pp_fused_kernel(
    const float* __restrict__ xyz,
    const float* __restrict__ cell_diag,
    const float* __restrict__ W1,
    const float* __restrict__ b1,
    const float* __restrict__ W2,
    const float* __restrict__ b2,
    float* __restrict__ out)
{
    __shared__ float sW1[HID], sb1[HID], sW2[HID];
    __shared__ float sBuf[NWARPS * BUFSZ];
    __shared__ float sRed[NWARPS];

    const int tid  = threadIdx.x;
    const int warp = tid >> 5;
    const int lane = tid & 31;

    if (tid < HID) {
        sW1[tid] = W1[tid];
        sb1[tid] = b1[tid];
        sW2[tid] = W2[tid];
    }
    __syncthreads();

    const float Lx = __ldg(&cell_diag[0]);
    const float Ly = __ldg(&cell_diag[1]);
    const float Lz = __ldg(&cell_diag[2]);
    const float hLx = 0.5f * Lx, hLy = 0.5f * Ly, hLz = 0.5f * Lz;
    const float b2v = __ldg(&b2[0]);

    float acc = 0.0f;
    unsigned int cnt = 0, processed = 0;   // per-warp (uniform) ring state
    float* buf = &sBuf[warp * BUFSZ];

    // 2 blocks per balanced row-pair: block = 2*i + h
    const int ipair = (int)(blockIdx.x >> 1);
    const int half  = (int)(blockIdx.x & 1);
    const int vwarp = half * NWARPS + warp;        // 0..7
    const int rows[2] = { ipair, NPART - 1 - ipair };

    #pragma unroll
    for (int r = 0; r < 2; ++r) {
        const int i = rows[r];
        const float xi = __ldg(&xyz[3 * i + 0]);
        const float yi = __ldg(&xyz[3 * i + 1]);
        const float zi = __ldg(&xyz[3 * i + 2]);

        for (int base = i + 1 + vwarp * 32; base < NPART; base += 2 * NTHREADS) {
            const int j = base + lane;
            const bool valid = (j < NPART);

            float dx = 0.f, dy = 0.f, dz = 0.f;
            if (valid) {
                dx = __ldg(&xyz[3 * j + 0]) - xi;
                dy = __ldg(&xyz[3 * j + 1]) - yi;
                dz = __ldg(&xyz[3 * j + 2]) - zi;
                if (dx >= hLx) dx -= Lx; else if (dx < -hLx) dx += Lx;
                if (dy >= hLy) dy -= Ly; else if (dy < -hLy) dy += Ly;
                if (dz >= hLz) dz -= Lz; else if (dz < -hLz) dz += Lz;
            }
            const float r2 = dx * dx + dy * dy + dz * dz;
            const bool hit = valid && (r2 < CUTOFF2) && (r2 > 0.0f);

            const unsigned int bal = __ballot_sync(0xFFFFFFFFu, hit);
            if (hit) {
                const unsigned int pos =
                    (cnt + __popc(bal & ((1u << lane) - 1u))) & (BUFSZ - 1);
                buf[pos] = sqrtf(r2);
            }
            cnt += __popc(bal);
            __syncwarp();

            if (cnt - processed >= 32) {
                const float d = buf[(processed + lane) & (BUFSZ - 1)];
                acc += mlp_energy(d, sW1, sb1, sW2, b2v);
                processed += 32;
                __syncwarp();
            }
        }
    }

    // flush remainder (< 32 pending distances)
    {
        const unsigned int rem = cnt - processed;
        if (rem > 0) {
            const float d = (lane < rem)
                ? buf[(processed + lane) & (BUFSZ - 1)] : 1.0f;
            const float e = mlp_energy(d, sW1, sb1, sW2, b2v);
            if (lane < rem) acc += e;
        }
    }

    // block reduction
    #pragma unroll
    for (int off = 16; off > 0; off >>= 1)
        acc += __shfl_xor_sync(0xFFFFFFFFu, acc, off);
    if (lane == 0) sRed[warp] = acc;
    __syncthreads();

    if (tid == 0) {
        const float bsum = sRed[0] + sRed[1] + sRed[2] + sRed[3];
        atomicAdd(&g_energy_accum, (double)bsum);
        __threadfence();
        const unsigned int ticket = atomicAdd(&g_block_count, 1u);
        if (ticket == gridDim.x - 1) {
            // all partials visible; finalize and reset for next graph replay
            const double total = atomicAdd(&g_energy_accum, 0.0);
            out[0] = (float)total;
            g_energy_accum = 0.0;
            g_block_count = 0;
            __threadfence();
        }
    }
}

extern "C" void kernel_launch(void* const* d_in, const int* in_sizes, int n_in,
                              void* d_out, int out_size) {
    const float* xyz       = (const float*)d_in[0];
    const float* cell_diag = (const float*)d_in[1];
    const float* W1        = (const float*)d_in[2];
    const float* b1        = (const float*)d_in[3];
    const float* W2        = (const float*)d_in[4];
    const float* b2        = (const float*)d_in[5];
    float* out = (float*)d_out;

    pp_fused_kernel<<<NPART, NTHREADS>>>(xyz, cell_diag, W1, b1, W2, b2, out);
}

// round 10
// speedup vs baseline: 2.5890x; 1.1345x over previous
#include <cuda_runtime.h>
#include <cuda_bf16.h>

#define NPART 2048
#define HID 32
#define CUTOFF 2.5f
#define CUTOFF2 6.25f
#define NTHREADS 128
#define NWARPS 4
#define M_TAB 8192

__device__ double g_energy_accum = 0.0;
__device__ unsigned int g_block_count = 0;
__device__ float g_table[M_TAB + 1];
__device__ float g_sx[NPART], g_sy[NPART], g_sz[NPART];

// Build energy table e(d) (exact tanhf) + SoA transpose of coordinates.
__global__ void __launch_bounds__(256) pp_table_kernel(
    const float* __restrict__ xyz,
    const float* __restrict__ W1,
    const float* __restrict__ b1,
    const float* __restrict__ W2,
    const float* __restrict__ b2)
{
    const int t = blockIdx.x * blockDim.x + threadIdx.x;

    if (t <= M_TAB) {
        const float d = (CUTOFF / (float)M_TAB) * (float)t;
        float e = __ldg(&b2[0]);
        #pragma unroll
        for (int k = 0; k < HID; ++k) {
            e = fmaf(__ldg(&W2[k]), tanhf(fmaf(d, __ldg(&W1[k]), __ldg(&b1[k]))), e);
        }
        g_table[t] = e;
    }

    if (t < NPART * 3) {
        const float v = xyz[t];
        const int p = t / 3, c = t - 3 * p;
        if (c == 0)      g_sx[p] = v;
        else if (c == 1) g_sy[p] = v;
        else             g_sz[p] = v;
    }
}

__global__ void __launch_bounds__(NTHREADS) pp_pair_kernel(
    const float* __restrict__ cell_diag,
    float* __restrict__ out)
{
    __shared__ float sRed[NWARPS];

    const int tid  = threadIdx.x;
    const int warp = tid >> 5;
    const int lane = tid & 31;

    const float Lx = __ldg(&cell_diag[0]);
    const float Ly = __ldg(&cell_diag[1]);
    const float Lz = __ldg(&cell_diag[2]);
    const float iLx = __frcp_rn(Lx), iLy = __frcp_rn(Ly), iLz = __frcp_rn(Lz);
    const float tscale = (float)M_TAB / CUTOFF;

    float acc = 0.0f;

    // 2 blocks per balanced row-pair: block = 2*ipair + half
    const int ipair = (int)(blockIdx.x >> 1);
    const int half  = (int)(blockIdx.x & 1);
    const int vwarp = half * NWARPS + warp;        // 0..7
    const int rows[2] = { ipair, NPART - 1 - ipair };

    #pragma unroll
    for (int r = 0; r < 2; ++r) {
        const int i = rows[r];
        const float xi = g_sx[i], yi = g_sy[i], zi = g_sz[i];

        for (int base = i + 1 + vwarp * 32; base < NPART; base += 2 * NTHREADS) {
            const int j  = base + lane;
            const int jc = (j < NPART) ? j : (NPART - 1);   // clamp for safe load

            float dx = g_sx[jc] - xi;
            float dy = g_sy[jc] - yi;
            float dz = g_sz[jc] - zi;
            // minimum-image via rint (boundary ties only matter beyond cutoff)
            dx = fmaf(-Lx, rintf(dx * iLx), dx);
            dy = fmaf(-Ly, rintf(dy * iLy), dy);
            dz = fmaf(-Lz, rintf(dz * iLz), dz);

            const float r2 = fmaf(dx, dx, fmaf(dy, dy, dz * dz));

            if (r2 < CUTOFF2 && r2 > 0.0f && j < NPART) {
                const float d = sqrtf(r2);
                const float u = d * tscale;
                const int   t = (int)u;
                const float f = u - (float)t;
                const float e0 = g_table[t];
                const float e1 = g_table[t + 1];
                acc += fmaf(e1 - e0, f, e0);
            }
        }
    }

    // block reduction
    #pragma unroll
    for (int off = 16; off > 0; off >>= 1)
        acc += __shfl_xor_sync(0xFFFFFFFFu, acc, off);
    if (lane == 0) sRed[warp] = acc;
    __syncthreads();

    if (tid == 0) {
        const float bsum = sRed[0] + sRed[1] + sRed[2] + sRed[3];
        atomicAdd(&g_energy_accum, (double)bsum);
        __threadfence();
        const unsigned int ticket = atomicAdd(&g_block_count, 1u);
        if (ticket == gridDim.x - 1) {
            const double total = atomicAdd(&g_energy_accum, 0.0);
            out[0] = (float)total;
            g_energy_accum = 0.0;
            g_block_count = 0;
            __threadfence();
        }
    }
}

extern "C" void kernel_launch(void* const* d_in, const int* in_sizes, int n_in,
                              void* d_out, int out_size) {
    const float* xyz       = (const float*)d_in[0];
    const float* cell_diag = (const float*)d_in[1];
    const float* W1        = (const float*)d_in[2];
    const float* b1        = (const float*)d_in[3];
    const float* W2        = (const float*)d_in[4];
    const float* b2        = (const float*)d_in[5];
    float* out = (float*)d_out;

    // 8193 table entries + 6144 transpose elements: 33 blocks x 256 covers both
    pp_table_kernel<<<(M_TAB + 1 + 255) / 256, 256>>>(xyz, W1, b1, W2, b2);
    pp_pair_kernel<<<NPART, NTHREADS>>>(cell_diag, out);
}

// round 11
// speedup vs baseline: 2.5939x; 1.0019x over previous
#include <cuda_runtime.h>
#include <cuda_bf16.h>

#define NPART 2048
#define HID 32
#define CUTOFF 2.5f
#define CUTOFF2 6.25f
#define NTHREADS 256
#define NWARPS 8
#define NBLOCKS 512
#define M_TAB 2048

__device__ double g_energy_accum = 0.0;
__device__ unsigned int g_block_count = 0;
__device__ float g_table[M_TAB + 1];
__device__ float g_sx[NPART], g_sy[NPART], g_sz[NPART];

// Build energy table e(d) (exact tanhf) + SoA transpose of coordinates.
__global__ void __launch_bounds__(256) pp_table_kernel(
    const float* __restrict__ xyz,
    const float* __restrict__ W1,
    const float* __restrict__ b1,
    const float* __restrict__ W2,
    const float* __restrict__ b2)
{
    const int t = blockIdx.x * blockDim.x + threadIdx.x;

    if (t <= M_TAB) {
        const float d = (CUTOFF / (float)M_TAB) * (float)t;
        float e = __ldg(&b2[0]);
        #pragma unroll
        for (int k = 0; k < HID; ++k) {
            e = fmaf(__ldg(&W2[k]), tanhf(fmaf(d, __ldg(&W1[k]), __ldg(&b1[k]))), e);
        }
        g_table[t] = e;
    }

    if (t < NPART * 3) {
        const float v = xyz[t];
        const int p = t / 3, c = t - 3 * p;
        if (c == 0)      g_sx[p] = v;
        else if (c == 1) g_sy[p] = v;
        else             g_sz[p] = v;
    }
}

__global__ void __launch_bounds__(NTHREADS) pp_pair_kernel(
    const float* __restrict__ cell_diag,
    float* __restrict__ out)
{
    __shared__ float sRed[NWARPS];

    const int tid  = threadIdx.x;
    const int warp = tid >> 5;
    const int lane = tid & 31;

    const float Lx = __ldg(&cell_diag[0]);
    const float Ly = __ldg(&cell_diag[1]);
    const float Lz = __ldg(&cell_diag[2]);
    const float iLx = __frcp_rn(Lx), iLy = __frcp_rn(Ly), iLz = __frcp_rn(Lz);
    const float tscale = (float)M_TAB / CUTOFF;

    float acc = 0.0f;

    // Each block handles 2 balanced row-pairs (4 rows total):
    //   ipair0 = blockIdx, ipair1 = blockIdx + NBLOCKS
    const int b = (int)blockIdx.x;
    const int rows[4] = { b,            NPART - 1 - b,
                          b + NBLOCKS,  NPART - 1 - (b + NBLOCKS) };

    #pragma unroll
    for (int r = 0; r < 4; ++r) {
        const int i = rows[r];
        const float xi = g_sx[i], yi = g_sy[i], zi = g_sz[i];

        for (int base = i + 1 + warp * 32; base < NPART; base += NTHREADS) {
            const int j  = base + lane;
            const int jc = (j < NPART) ? j : (NPART - 1);   // clamp for safe load

            float dx = g_sx[jc] - xi;
            float dy = g_sy[jc] - yi;
            float dz = g_sz[jc] - zi;
            // minimum-image via rint (boundary ties only matter beyond cutoff)
            dx = fmaf(-Lx, rintf(dx * iLx), dx);
            dy = fmaf(-Ly, rintf(dy * iLy), dy);
            dz = fmaf(-Lz, rintf(dz * iLz), dz);

            const float r2 = fmaf(dx, dx, fmaf(dy, dy, dz * dz));

            if (r2 < CUTOFF2 && r2 > 0.0f && j < NPART) {
                const float d = sqrtf(r2);
                const float u = d * tscale;
                const int   t = (int)u;
                const float f = u - (float)t;
                const float e0 = g_table[t];
                const float e1 = g_table[t + 1];
                acc += fmaf(e1 - e0, f, e0);
            }
        }
    }

    // block reduction
    #pragma unroll
    for (int off = 16; off > 0; off >>= 1)
        acc += __shfl_xor_sync(0xFFFFFFFFu, acc, off);
    if (lane == 0) sRed[warp] = acc;
    __syncthreads();

    if (tid < 32) {
        float bsum = (tid < NWARPS) ? sRed[tid] : 0.0f;
        #pragma unroll
        for (int off = 4; off > 0; off >>= 1)
            bsum += __shfl_xor_sync(0xFFFFFFFFu, bsum, off);

        if (tid == 0) {
            atomicAdd(&g_energy_accum, (double)bsum);
            __threadfence();
            const unsigned int ticket = atomicAdd(&g_block_count, 1u);
            if (ticket == gridDim.x - 1) {
                const double total = atomicAdd(&g_energy_accum, 0.0);
                out[0] = (float)total;
                g_energy_accum = 0.0;
                g_block_count = 0;
                __threadfence();
            }
        }
    }
}

extern "C" void kernel_launch(void* const* d_in, const int* in_sizes, int n_in,
                              void* d_out, int out_size) {
    const float* xyz       = (const float*)d_in[0];
    const float* cell_diag = (const float*)d_in[1];
    const float* W1        = (const float*)d_in[2];
    const float* b1        = (const float*)d_in[3];
    const float* W2        = (const float*)d_in[4];
    const float* b2        = (const float*)d_in[5];
    float* out = (float*)d_out;

    // covers max(M_TAB+1, NPART*3) = 6144 work items
    pp_table_kernel<<<(NPART * 3 + 255) / 256, 256>>>(xyz, W1, b1, W2, b2);
    pp_pair_kernel<<<NBLOCKS, NTHREADS>>>(cell_diag, out);
}